// round 9
// baseline (speedup 1.0000x reference)
#include <cuda_runtime.h>
#include <math.h>

#define NN 768

// ---------------- scratch ----------------
__device__ float g_q[64*NN], g_k[64*NN], g_vT[NN*64];
__device__ float g_A[128*NN], g_B[128*NN];
__device__ float g_av[64*NN], g_g1[128*NN];
__device__ float g_Wp[128*64], g_bp[128];
__device__ float g_Sk[NN];
__device__ float g_s1[128], g_q1[128];
__device__ float g_sA[128], g_qA[128], g_sB[128], g_qB[128];
__device__ float g_sG[128], g_qG[128];

// ---------------- helpers ----------------
__device__ __forceinline__ float wsum(float v) {
    #pragma unroll
    for (int o = 16; o; o >>= 1) v += __shfl_xor_sync(0xffffffffu, v, o);
    return v;
}
__device__ __forceinline__ float wmax(float v) {
    #pragma unroll
    for (int o = 16; o; o >>= 1) v = fmaxf(v, __shfl_xor_sync(0xffffffffu, v, o));
    return v;
}

// wT[i*8+r] = W[(o0+r)*ldw + koff + i]
__device__ __forceinline__ void fillW8(float* wT, const float* __restrict__ W,
                                       int ldw, int o0, int koff) {
    #pragma unroll
    for (int v = threadIdx.x; v < 512; v += 256) {
        int i = v >> 3, r = v & 7;
        wT[v] = W[(o0 + r) * ldw + koff + i];
    }
}
// wT[i*4+r]
__device__ __forceinline__ void fillW4(float* wT, const float* __restrict__ W,
                                       int ldw, int o0, int koff) {
    if (threadIdx.x < 256) {
        int i = threadIdx.x >> 2, r = threadIdx.x & 3;
        wT[threadIdx.x] = W[(o0 + r) * ldw + koff + i];
    }
}

// 8 rows x 128 cols, K=64, X streamed. acc[4].
__device__ __forceinline__ void gemm8p(const float* __restrict__ X, int c0,
                                       const float* wT, float acc[4]) {
    int c = threadIdx.x & 127, rg = threadIdx.x >> 7;
    const float* xp = X + c0 + c;
    const float* wp = wT + rg * 4;
    #pragma unroll 8
    for (int i = 0; i < 64; i++) {
        float x = __ldg(xp + i * NN);
        float4 w = *(const float4*)(wp + i * 8);
        acc[0] = fmaf(w.x, x, acc[0]); acc[1] = fmaf(w.y, x, acc[1]);
        acc[2] = fmaf(w.z, x, acc[2]); acc[3] = fmaf(w.w, x, acc[3]);
    }
}
// Same with relu(nb[i].x*x+nb[i].y) on load.
__device__ __forceinline__ void gemm8n(const float* __restrict__ X, int c0,
                                       const float* wT, const float2* nb, float acc[4]) {
    int c = threadIdx.x & 127, rg = threadIdx.x >> 7;
    const float* xp = X + c0 + c;
    const float* wp = wT + rg * 4;
    #pragma unroll 8
    for (int i = 0; i < 64; i++) {
        float2 sb = nb[i];
        float x = fmaxf(fmaf(sb.x, __ldg(xp + i * NN), sb.y), 0.f);
        float4 w = *(const float4*)(wp + i * 8);
        acc[0] = fmaf(w.x, x, acc[0]); acc[1] = fmaf(w.y, x, acc[1]);
        acc[2] = fmaf(w.z, x, acc[2]); acc[3] = fmaf(w.w, x, acc[3]);
    }
}
// 4 rows x 128 cols, K=64, norm-on-load. acc[2].
__device__ __forceinline__ void gemm4n(const float* __restrict__ X, int c0,
                                       const float* wT, const float2* nb, float acc[2]) {
    int c = threadIdx.x & 127, rg = threadIdx.x >> 7;
    const float* xp = X + c0 + c;
    const float* wp = wT + rg * 2;
    #pragma unroll 8
    for (int i = 0; i < 64; i++) {
        float2 sb = nb[i];
        float x = fmaxf(fmaf(sb.x, __ldg(xp + i * NN), sb.y), 0.f);
        float2 w = *(const float2*)(wp + i * 4);
        acc[0] = fmaf(w.x, x, acc[0]); acc[1] = fmaf(w.y, x, acc[1]);
    }
}

// Per-row (8 rows/block) sum & sumsq -> atomicAdd into sdst/qdst.
__device__ __forceinline__ void rowstats8(const float vals[4], int o0,
                                          float* sdst, float* qdst) {
    __shared__ float rs[8][4], rq[8][4];
    int wid = threadIdx.x >> 5, lane = threadIdx.x & 31, rg = threadIdx.x >> 7;
    #pragma unroll
    for (int r = 0; r < 4; r++) {
        float s = wsum(vals[r]);
        float s2 = wsum(vals[r] * vals[r]);
        if (lane == 0) { rs[rg * 4 + r][wid & 3] = s; rq[rg * 4 + r][wid & 3] = s2; }
    }
    __syncthreads();
    if (threadIdx.x < 8) {
        float s  = rs[threadIdx.x][0] + rs[threadIdx.x][1] + rs[threadIdx.x][2] + rs[threadIdx.x][3];
        float q2 = rq[threadIdx.x][0] + rq[threadIdx.x][1] + rq[threadIdx.x][2] + rq[threadIdx.x][3];
        atomicAdd(&sdst[o0 + threadIdx.x], s);
        atomicAdd(&qdst[o0 + threadIdx.x], q2);
    }
}

// ---------------- kernels ----------------

// Zero all stats accumulators. Grid 7 x 256.
__global__ void k_zero()
{
    int t = blockIdx.x * 256 + threadIdx.x;
    if (t < 768) g_Sk[t] = 0.f;
    else if (t < 896)  g_s1[t - 768]  = 0.f;
    else if (t < 1024) g_q1[t - 896]  = 0.f;
    else if (t < 1152) g_sA[t - 1024] = 0.f;
    else if (t < 1280) g_qA[t - 1152] = 0.f;
    else if (t < 1408) g_sB[t - 1280] = 0.f;
    else if (t < 1536) g_qB[t - 1408] = 0.f;
    else if (t < 1664) g_sG[t - 1536] = 0.f;
    else               g_qG[t - 1664] = 0.f;
}

// q/k/v convs (8x128 tiles) + stage-1 stats + Sk atomics + W', b'. Grid 161 x 256.
__global__ void k_qkv(const float* __restrict__ d1, const float* __restrict__ d2,
                      const float* __restrict__ qw, const float* __restrict__ qb,
                      const float* __restrict__ kw, const float* __restrict__ kb,
                      const float* __restrict__ vw, const float* __restrict__ vb,
                      const float* __restrict__ mhw, const float* __restrict__ mhb,
                      const float* __restrict__ cw1, const float* __restrict__ cb1,
                      const float* __restrict__ shw)
{
    __shared__ float wT[512];
    __shared__ float skred[128];
    int b = blockIdx.x, tid = threadIdx.x;
    if (b < 144) {
        int grp = b / 48, lb = b % 48;
        int o0 = (lb / 6) * 8, c0 = (lb % 6) * 128;
        const float *W, *X, *Bb;
        if (grp == 0)      { W = qw; X = d1; Bb = qb; }
        else if (grp == 1) { W = kw; X = d2; Bb = kb; }
        else               { W = vw; X = d2; Bb = vb; }
        fillW8(wT, W, 64, o0, 0);
        __syncthreads();
        float acc[4] = {};
        gemm8p(X, c0, wT, acc);
        int c = tid & 127, rg = tid >> 7;
        int ob = o0 + rg * 4;
        float vals[4];
        #pragma unroll
        for (int r = 0; r < 4; r++) vals[r] = acc[r] + __ldg(Bb + ob + r);
        if (grp == 0) {
            #pragma unroll
            for (int r = 0; r < 4; r++) g_q[(ob + r) * NN + c0 + c] = vals[r];
            __syncthreads();
            rowstats8(vals, o0, g_s1, g_q1);
        } else if (grp == 1) {
            #pragma unroll
            for (int r = 0; r < 4; r++) g_k[(ob + r) * NN + c0 + c] = vals[r];
            float p = 0.f;
            #pragma unroll
            for (int r = 0; r < 4; r++) p = fmaf(__ldg(shw + 64 + ob + r), vals[r], p);
            if (rg == 1) skred[c] = p;
            __syncthreads();
            if (rg == 0) atomicAdd(&g_Sk[c0 + c], p + skred[c]);
            __syncthreads();
            rowstats8(vals, 64 + o0, g_s1, g_q1);
        } else {
            float4 vv;
            vv.x = vals[0]; vv.y = vals[1]; vv.z = vals[2]; vv.w = vals[3];
            *(float4*)&g_vT[(c0 + c) * 64 + ob] = vv;
        }
    } else if (b < 160) {
        // W'[row, d] = sum_i cw1[row, 64+i] * mhw[i, d]
        int r0 = (b - 144) * 8;
        int d = tid & 63, rg = tid >> 6;
        int row = r0 + rg * 2;
        float a0 = 0.f, a1 = 0.f;
        #pragma unroll 8
        for (int i = 0; i < 64; i++) {
            float x = __ldg(mhw + i * 64 + d);
            a0 = fmaf(__ldg(cw1 + row * 128 + 64 + i), x, a0);
            a1 = fmaf(__ldg(cw1 + (row + 1) * 128 + 64 + i), x, a1);
        }
        g_Wp[row * 64 + d] = a0;
        g_Wp[(row + 1) * 64 + d] = a1;
    } else {
        if (tid < 128) {
            float s = __ldg(cb1 + tid);
            #pragma unroll 8
            for (int i = 0; i < 64; i++)
                s = fmaf(__ldg(cw1 + tid * 128 + 64 + i), __ldg(mhb + i), s);
            g_bp[tid] = s;
        }
    }
}

// A/B GEMM (8x128 tiles), stage-1 coeffs from accums, stage-2 stats atomics. Grid 192.
__global__ void k_AB(const float* __restrict__ w1, const float* __restrict__ b1,
                     const float* __restrict__ bn1g, const float* __restrict__ bn1b)
{
    __shared__ float wT[512];
    __shared__ float2 nb[64];
    int b = blockIdx.x, tid = threadIdx.x;
    int half = b / 96, lb = b % 96;
    int o0 = (lb / 6) * 8, c0 = (lb % 6) * 128;
    if (tid < 64) {
        int ch = half * 64 + tid;
        float m = g_s1[ch] * (1.f / NN);
        float v = g_q1[ch] * (1.f / NN) - m * m;
        float si = rsqrtf(v + 1e-3f);
        float vn = v * si * si;
        float sb = rsqrtf(vn + 1e-5f);
        float sc = si * sb * __ldg(bn1g + ch);
        nb[tid] = make_float2(sc, -m * sc + __ldg(bn1b + ch));
    }
    fillW8(wT, w1, 128, o0, half * 64);
    __syncthreads();
    float acc[4] = {};
    gemm8n(half ? g_k : g_q, c0, wT, nb, acc);
    int c = tid & 127, rg = tid >> 7;
    int ob = o0 + rg * 4;
    float vals[4];
    if (half == 0) {
        #pragma unroll
        for (int r = 0; r < 4; r++) {
            vals[r] = acc[r];
            g_A[(ob + r) * NN + c0 + c] = vals[r];
        }
    } else {
        #pragma unroll
        for (int r = 0; r < 4; r++) {
            vals[r] = acc[r] + __ldg(b1 + ob + r);
            g_B[(ob + r) * NN + c0 + c] = vals[r];
        }
    }
    __syncthreads();
    rowstats8(vals, o0, half ? g_sB : g_sA, half ? g_qB : g_qA);
}

// score_pre, 32x64 tiles. Grid 288 x 256.  (Sq + consts cancel in softmax.)
__global__ void __launch_bounds__(256)
k_score(const float* __restrict__ w2,
        const float* __restrict__ bn2g, const float* __restrict__ bn2b,
        float* __restrict__ out)
{
    __shared__ float As[64 * 32];
    __shared__ float Bs[64 * 64];
    __shared__ float2 scb[128];
    __shared__ float w2s[128];
    __shared__ float Sks[64];
    int b = blockIdx.x, tid = threadIdx.x;
    int n0 = (b / 12) * 32, m0 = (b % 12) * 64;
    if (tid < 128) {
        float mA = g_sA[tid] * (1.f / NN), mB = g_sB[tid] * (1.f / NN);
        float vA = g_qA[tid] * (1.f / NN) - mA * mA;
        float vB = g_qB[tid] * (1.f / NN) - mB * mB;
        float m2 = mA + mB, v2 = vA + vB;
        float si = rsqrtf(v2 + 1e-3f);
        float vn = v2 * si * si;
        float sb = rsqrtf(vn + 1e-5f);
        float sc = si * sb * __ldg(bn2g + tid);
        scb[tid] = make_float2(sc, -m2 * sc + __ldg(bn2b + tid));
        w2s[tid] = __ldg(w2 + tid);
    } else if (tid < 192) {
        Sks[tid - 128] = g_Sk[m0 + tid - 128];
    }
    __syncthreads();

    int tx = tid & 15, ty = tid >> 4;
    float acc[2][4] = {};
    #pragma unroll
    for (int ch = 0; ch < 2; ch++) {
        #pragma unroll
        for (int v = tid; v < 512; v += 256) {
            int o = v >> 3, j4 = (v & 7) << 2;
            int og = ch * 64 + o;
            float2 sb = scb[og];
            float4 a = *(const float4*)&g_A[og * NN + n0 + j4];
            a.x = fmaf(sb.x, a.x, sb.y); a.y = fmaf(sb.x, a.y, sb.y);
            a.z = fmaf(sb.x, a.z, sb.y); a.w = fmaf(sb.x, a.w, sb.y);
            *(float4*)&As[o * 32 + j4] = a;
        }
        #pragma unroll
        for (int v = tid; v < 1024; v += 256) {
            int o = v >> 4, j4 = (v & 15) << 2;
            int og = ch * 64 + o;
            float s = scb[og].x;
            float4 bv = *(const float4*)&g_B[og * NN + m0 + j4];
            bv.x *= s; bv.y *= s; bv.z *= s; bv.w *= s;
            *(float4*)&Bs[o * 64 + j4] = bv;
        }
        __syncthreads();
        #pragma unroll 4
        for (int o = 0; o < 64; o++) {
            float2 a = *(const float2*)&As[o * 32 + ty * 2];
            float4 bv = *(const float4*)&Bs[o * 64 + tx * 4];
            float w = w2s[ch * 64 + o];
            acc[0][0] = fmaf(w, fmaxf(a.x + bv.x, 0.f), acc[0][0]);
            acc[0][1] = fmaf(w, fmaxf(a.x + bv.y, 0.f), acc[0][1]);
            acc[0][2] = fmaf(w, fmaxf(a.x + bv.z, 0.f), acc[0][2]);
            acc[0][3] = fmaf(w, fmaxf(a.x + bv.w, 0.f), acc[0][3]);
            acc[1][0] = fmaf(w, fmaxf(a.y + bv.x, 0.f), acc[1][0]);
            acc[1][1] = fmaf(w, fmaxf(a.y + bv.y, 0.f), acc[1][1]);
            acc[1][2] = fmaf(w, fmaxf(a.y + bv.z, 0.f), acc[1][2]);
            acc[1][3] = fmaf(w, fmaxf(a.y + bv.w, 0.f), acc[1][3]);
        }
        __syncthreads();
    }
    #pragma unroll
    for (int rn = 0; rn < 2; rn++) {
        int n = n0 + ty * 2 + rn;
        float4 o4;
        o4.x = acc[rn][0] + Sks[tx * 4 + 0];
        o4.y = acc[rn][1] + Sks[tx * 4 + 1];
        o4.z = acc[rn][2] + Sks[tx * 4 + 2];
        o4.w = acc[rn][3] + Sks[tx * 4 + 3];
        *(float4*)&out[n * NN + m0 + tx * 4] = o4;
    }
}

// Fused softmax + AV: 4 rows per block. Grid 192 x 256.
__global__ void __launch_bounds__(256)
k_avsm(float* __restrict__ score)
{
    __shared__ float Ps[4 * 768];
    __shared__ float mred[4][2], sred[4][2];
    __shared__ float hred[128][2];
    __shared__ float tr[64 * 4];
    int b = blockIdx.x, tid = threadIdx.x;
    int n0 = b * 4;
    int wid = tid >> 5, lane = tid & 31;
    int row = wid >> 1, hf = wid & 1;

    // softmax: 2 warps per row, 12 elems per lane
    float v[12];
    const int base = (n0 + row) * NN + hf * 384 + lane;
    float mx = -1e30f;
    #pragma unroll
    for (int i = 0; i < 12; i++) { v[i] = __ldg(score + base + i * 32); mx = fmaxf(mx, v[i]); }
    mx = wmax(mx);
    if (lane == 0) mred[row][hf] = mx;
    __syncthreads();
    mx = fmaxf(mred[row][0], mred[row][1]);
    float s = 0.f;
    #pragma unroll
    for (int i = 0; i < 12; i++) { v[i] = __expf(v[i] - mx); s += v[i]; }
    s = wsum(s);
    if (lane == 0) sred[row][hf] = s;
    __syncthreads();
    float inv = 1.f / (sred[row][0] + sred[row][1]);
    #pragma unroll
    for (int i = 0; i < 12; i++) {
        float p = v[i] * inv;
        Ps[row * 768 + hf * 384 + lane + i * 32] = p;
        score[base + i * 32] = p;
    }
    __syncthreads();

    // AV: split-m, thread = (mh, n, d-pair)
    int mh = tid >> 7, nn = (tid >> 5) & 3, dp = tid & 31;
    int d0 = dp * 2;
    const float* psp = Ps + nn * 768 + mh * 384;
    float a0 = 0.f, a1 = 0.f;
    #pragma unroll 8
    for (int m = 0; m < 384; m++) {
        float2 vv = __ldg((const float2*)(g_vT + (mh * 384 + m) * 64 + d0));
        float p = psp[m];
        a0 = fmaf(p, vv.x, a0); a1 = fmaf(p, vv.y, a1);
    }
    if (mh == 1) { hred[nn * 32 + dp][0] = a0; hred[nn * 32 + dp][1] = a1; }
    __syncthreads();
    if (mh == 0) {
        a0 += hred[nn * 32 + dp][0];
        a1 += hred[nn * 32 + dp][1];
        tr[d0 * 4 + nn] = a0;
        tr[(d0 + 1) * 4 + nn] = a1;
    }
    __syncthreads();
    if (tid < 64) *(float4*)&g_av[tid * NN + n0] = *(float4*)&tr[tid * 4];
}

// g1 = cw1[:,:64]@desc1 + W'@av + b'; bn1d stats atomics. Grid 96 x 256.
__global__ void k_g1(const float* __restrict__ cw1, const float* __restrict__ desc1)
{
    __shared__ float wT[512];
    int b = blockIdx.x, tid = threadIdx.x;
    int o0 = (b / 6) * 8, c0 = (b % 6) * 128;
    float acc[4] = {};
    fillW8(wT, cw1, 128, o0, 0);
    __syncthreads();
    gemm8p(desc1, c0, wT, acc);
    __syncthreads();
    fillW8(wT, g_Wp, 64, o0, 0);
    __syncthreads();
    gemm8p(g_av, c0, wT, acc);
    int c = tid & 127, rg = tid >> 7;
    int ob = o0 + rg * 4;
    float vals[4];
    #pragma unroll
    for (int r = 0; r < 4; r++) {
        vals[r] = acc[r] + g_bp[ob + r];
        g_g1[(ob + r) * NN + c0 + c] = vals[r];
    }
    __syncthreads();
    rowstats8(vals, o0, g_sG, g_qG);
}

// out_desc = desc1 + cw2 @ relu(norm(g1)) + cb2. 4-row tiles, Grid 96 x 256.
__global__ void k_final(const float* __restrict__ cw2, const float* __restrict__ cb2,
                        const float* __restrict__ cbg, const float* __restrict__ cbb,
                        const float* __restrict__ desc1, float* __restrict__ out)
{
    __shared__ float wT[256];
    __shared__ float2 ncf[128];
    int b = blockIdx.x, tid = threadIdx.x;
    int o0 = (b / 6) * 4, c0 = (b % 6) * 128;
    if (tid < 128) {
        float m = g_sG[tid] * (1.f / NN);
        float v = g_qG[tid] * (1.f / NN) - m * m;
        float sc = rsqrtf(v + 1e-5f) * __ldg(cbg + tid);
        ncf[tid] = make_float2(sc, -m * sc + __ldg(cbb + tid));
    }
    float acc[2] = {};
    fillW4(wT, cw2, 128, o0, 0);
    __syncthreads();
    gemm4n(g_g1, c0, wT, ncf, acc);
    __syncthreads();
    fillW4(wT, cw2, 128, o0, 64);
    __syncthreads();
    gemm4n(g_g1 + 64 * NN, c0, wT, ncf + 64, acc);
    int c = tid & 127, rg = tid >> 7;
    int ob = o0 + rg * 2;
    #pragma unroll
    for (int r = 0; r < 2; r++)
        out[(ob + r) * NN + c0 + c] =
            acc[r] + __ldg(cb2 + ob + r) + __ldg(desc1 + (ob + r) * NN + c0 + c);
}

// ---------------- launch ----------------
extern "C" void kernel_launch(void* const* d_in, const int* in_sizes, int n_in,
                              void* d_out, int out_size)
{
    const float* desc1 = (const float*)d_in[0];
    const float* desc2 = (const float*)d_in[1];
    const float* qw  = (const float*)d_in[2];  const float* qb  = (const float*)d_in[3];
    const float* kw  = (const float*)d_in[4];  const float* kb  = (const float*)d_in[5];
    const float* vw  = (const float*)d_in[6];  const float* vb  = (const float*)d_in[7];
    const float* mhw = (const float*)d_in[8];  const float* mhb = (const float*)d_in[9];
    const float* cw1 = (const float*)d_in[10]; const float* cb1 = (const float*)d_in[11];
    const float* cbg = (const float*)d_in[12]; const float* cbb = (const float*)d_in[13];
    const float* cw2 = (const float*)d_in[14]; const float* cb2 = (const float*)d_in[15];
    const float* shw = (const float*)d_in[16];
    const float* bn1g = (const float*)d_in[18]; const float* bn1b = (const float*)d_in[19];
    const float* sw1 = (const float*)d_in[20]; const float* sb1 = (const float*)d_in[21];
    const float* bn2g = (const float*)d_in[22]; const float* bn2b = (const float*)d_in[23];
    const float* sw2 = (const float*)d_in[24];

    float* out = (float*)d_out;
    float* out_desc  = out;
    float* out_score = out + 64 * NN;

    k_zero<<<7, 256>>>();
    k_qkv<<<161, 256>>>(desc1, desc2, qw, qb, kw, kb, vw, vb, mhw, mhb, cw1, cb1, shw);
    k_AB<<<192, 256>>>(sw1, sb1, bn1g, bn1b);
    k_score<<<288, 256>>>(sw2, bn2g, bn2b, out_score);
    k_avsm<<<192, 256>>>(out_score);
    k_g1<<<96, 256>>>(cw1, desc1);
    k_final<<<96, 256>>>(cw2, cb2, cbg, cbb, desc1, out_desc);
}

// round 10
// speedup vs baseline: 1.0183x; 1.0183x over previous
#include <cuda_runtime.h>
#include <math.h>

#define NN 768

// ---------------- scratch ----------------
__device__ float g_q[64*NN], g_k[64*NN], g_vT[NN*64];
__device__ float g_A[128*NN], g_B[128*NN];
__device__ float g_av[64*NN], g_g1[128*NN];
__device__ float g_Wp[128*64], g_bp[128];
__device__ float g_Sk[NN];
__device__ float g_s1[128], g_q1[128];
__device__ float g_sA[128], g_qA[128], g_sB[128], g_qB[128];
__device__ float g_sG[128], g_qG[128];

// ---------------- helpers ----------------
__device__ __forceinline__ float wsum(float v) {
    #pragma unroll
    for (int o = 16; o; o >>= 1) v += __shfl_xor_sync(0xffffffffu, v, o);
    return v;
}
__device__ __forceinline__ float wmax(float v) {
    #pragma unroll
    for (int o = 16; o; o >>= 1) v = fmaxf(v, __shfl_xor_sync(0xffffffffu, v, o));
    return v;
}

// wT[i*8+r] = W[(o0+r)*ldw + koff + i]
__device__ __forceinline__ void fillW8(float* wT, const float* __restrict__ W,
                                       int ldw, int o0, int koff) {
    #pragma unroll
    for (int v = threadIdx.x; v < 512; v += 256) {
        int i = v >> 3, r = v & 7;
        wT[v] = W[(o0 + r) * ldw + koff + i];
    }
}
// wT[i*4+r]
__device__ __forceinline__ void fillW4(float* wT, const float* __restrict__ W,
                                       int ldw, int o0, int koff) {
    if (threadIdx.x < 256) {
        int i = threadIdx.x >> 2, r = threadIdx.x & 3;
        wT[threadIdx.x] = W[(o0 + r) * ldw + koff + i];
    }
}

// 8 rows x 128 cols, K=64, X streamed. acc[4].
__device__ __forceinline__ void gemm8p(const float* __restrict__ X, int c0,
                                       const float* wT, float acc[4]) {
    int c = threadIdx.x & 127, rg = threadIdx.x >> 7;
    const float* xp = X + c0 + c;
    const float* wp = wT + rg * 4;
    #pragma unroll 8
    for (int i = 0; i < 64; i++) {
        float x = __ldg(xp + i * NN);
        float4 w = *(const float4*)(wp + i * 8);
        acc[0] = fmaf(w.x, x, acc[0]); acc[1] = fmaf(w.y, x, acc[1]);
        acc[2] = fmaf(w.z, x, acc[2]); acc[3] = fmaf(w.w, x, acc[3]);
    }
}
// Same with relu(nb[i].x*x+nb[i].y) on load.
__device__ __forceinline__ void gemm8n(const float* __restrict__ X, int c0,
                                       const float* wT, const float2* nb, float acc[4]) {
    int c = threadIdx.x & 127, rg = threadIdx.x >> 7;
    const float* xp = X + c0 + c;
    const float* wp = wT + rg * 4;
    #pragma unroll 8
    for (int i = 0; i < 64; i++) {
        float2 sb = nb[i];
        float x = fmaxf(fmaf(sb.x, __ldg(xp + i * NN), sb.y), 0.f);
        float4 w = *(const float4*)(wp + i * 8);
        acc[0] = fmaf(w.x, x, acc[0]); acc[1] = fmaf(w.y, x, acc[1]);
        acc[2] = fmaf(w.z, x, acc[2]); acc[3] = fmaf(w.w, x, acc[3]);
    }
}
// 4 rows x 128 cols, K=64, norm-on-load. acc[2].
__device__ __forceinline__ void gemm4n(const float* __restrict__ X, int c0,
                                       const float* wT, const float2* nb, float acc[2]) {
    int c = threadIdx.x & 127, rg = threadIdx.x >> 7;
    const float* xp = X + c0 + c;
    const float* wp = wT + rg * 2;
    #pragma unroll 8
    for (int i = 0; i < 64; i++) {
        float2 sb = nb[i];
        float x = fmaxf(fmaf(sb.x, __ldg(xp + i * NN), sb.y), 0.f);
        float2 w = *(const float2*)(wp + i * 4);
        acc[0] = fmaf(w.x, x, acc[0]); acc[1] = fmaf(w.y, x, acc[1]);
    }
}

// Per-row (8 rows/block) sum & sumsq -> atomicAdd into sdst/qdst.
__device__ __forceinline__ void rowstats8(const float vals[4], int o0,
                                          float* sdst, float* qdst) {
    __shared__ float rs[8][4], rq[8][4];
    int wid = threadIdx.x >> 5, lane = threadIdx.x & 31, rg = threadIdx.x >> 7;
    #pragma unroll
    for (int r = 0; r < 4; r++) {
        float s = wsum(vals[r]);
        float s2 = wsum(vals[r] * vals[r]);
        if (lane == 0) { rs[rg * 4 + r][wid & 3] = s; rq[rg * 4 + r][wid & 3] = s2; }
    }
    __syncthreads();
    if (threadIdx.x < 8) {
        float s  = rs[threadIdx.x][0] + rs[threadIdx.x][1] + rs[threadIdx.x][2] + rs[threadIdx.x][3];
        float q2 = rq[threadIdx.x][0] + rq[threadIdx.x][1] + rq[threadIdx.x][2] + rq[threadIdx.x][3];
        atomicAdd(&sdst[o0 + threadIdx.x], s);
        atomicAdd(&qdst[o0 + threadIdx.x], q2);
    }
}

// ---------------- kernels ----------------

// Zero all stats accumulators. Grid 7 x 256.
__global__ void k_zero()
{
    int t = blockIdx.x * 256 + threadIdx.x;
    if (t < 768) g_Sk[t] = 0.f;
    else if (t < 896)  g_s1[t - 768]  = 0.f;
    else if (t < 1024) g_q1[t - 896]  = 0.f;
    else if (t < 1152) g_sA[t - 1024] = 0.f;
    else if (t < 1280) g_qA[t - 1152] = 0.f;
    else if (t < 1408) g_sB[t - 1280] = 0.f;
    else if (t < 1536) g_qB[t - 1408] = 0.f;
    else if (t < 1664) g_sG[t - 1536] = 0.f;
    else               g_qG[t - 1664] = 0.f;
}

// q/k/v convs (8x128 tiles) + stage-1 stats + Sk atomics + W', b'. Grid 161 x 256.
__global__ void k_qkv(const float* __restrict__ d1, const float* __restrict__ d2,
                      const float* __restrict__ qw, const float* __restrict__ qb,
                      const float* __restrict__ kw, const float* __restrict__ kb,
                      const float* __restrict__ vw, const float* __restrict__ vb,
                      const float* __restrict__ mhw, const float* __restrict__ mhb,
                      const float* __restrict__ cw1, const float* __restrict__ cb1,
                      const float* __restrict__ shw)
{
    __shared__ float wT[512];
    __shared__ float skred[128];
    int b = blockIdx.x, tid = threadIdx.x;
    if (b < 144) {
        int grp = b / 48, lb = b % 48;
        int o0 = (lb / 6) * 8, c0 = (lb % 6) * 128;
        const float *W, *X, *Bb;
        if (grp == 0)      { W = qw; X = d1; Bb = qb; }
        else if (grp == 1) { W = kw; X = d2; Bb = kb; }
        else               { W = vw; X = d2; Bb = vb; }
        fillW8(wT, W, 64, o0, 0);
        __syncthreads();
        float acc[4] = {};
        gemm8p(X, c0, wT, acc);
        int c = tid & 127, rg = tid >> 7;
        int ob = o0 + rg * 4;
        float vals[4];
        #pragma unroll
        for (int r = 0; r < 4; r++) vals[r] = acc[r] + __ldg(Bb + ob + r);
        if (grp == 0) {
            #pragma unroll
            for (int r = 0; r < 4; r++) g_q[(ob + r) * NN + c0 + c] = vals[r];
            __syncthreads();
            rowstats8(vals, o0, g_s1, g_q1);
        } else if (grp == 1) {
            #pragma unroll
            for (int r = 0; r < 4; r++) g_k[(ob + r) * NN + c0 + c] = vals[r];
            float p = 0.f;
            #pragma unroll
            for (int r = 0; r < 4; r++) p = fmaf(__ldg(shw + 64 + ob + r), vals[r], p);
            if (rg == 1) skred[c] = p;
            __syncthreads();
            if (rg == 0) atomicAdd(&g_Sk[c0 + c], p + skred[c]);
            __syncthreads();
            rowstats8(vals, 64 + o0, g_s1, g_q1);
        } else {
            float4 vv;
            vv.x = vals[0]; vv.y = vals[1]; vv.z = vals[2]; vv.w = vals[3];
            *(float4*)&g_vT[(c0 + c) * 64 + ob] = vv;
        }
    } else if (b < 160) {
        // W'[row, d] = sum_i cw1[row, 64+i] * mhw[i, d]
        int r0 = (b - 144) * 8;
        int d = tid & 63, rg = tid >> 6;
        int row = r0 + rg * 2;
        float a0 = 0.f, a1 = 0.f;
        #pragma unroll 8
        for (int i = 0; i < 64; i++) {
            float x = __ldg(mhw + i * 64 + d);
            a0 = fmaf(__ldg(cw1 + row * 128 + 64 + i), x, a0);
            a1 = fmaf(__ldg(cw1 + (row + 1) * 128 + 64 + i), x, a1);
        }
        g_Wp[row * 64 + d] = a0;
        g_Wp[(row + 1) * 64 + d] = a1;
    } else {
        if (tid < 128) {
            float s = __ldg(cb1 + tid);
            #pragma unroll 8
            for (int i = 0; i < 64; i++)
                s = fmaf(__ldg(cw1 + tid * 128 + 64 + i), __ldg(mhb + i), s);
            g_bp[tid] = s;
        }
    }
}

// A/B GEMM (8x128 tiles), stage-1 coeffs from accums, stage-2 stats atomics. Grid 192.
__global__ void k_AB(const float* __restrict__ w1, const float* __restrict__ b1,
                     const float* __restrict__ bn1g, const float* __restrict__ bn1b)
{
    __shared__ float wT[512];
    __shared__ float2 nb[64];
    int b = blockIdx.x, tid = threadIdx.x;
    int half = b / 96, lb = b % 96;
    int o0 = (lb / 6) * 8, c0 = (lb % 6) * 128;
    if (tid < 64) {
        int ch = half * 64 + tid;
        float m = g_s1[ch] * (1.f / NN);
        float v = g_q1[ch] * (1.f / NN) - m * m;
        float si = rsqrtf(v + 1e-3f);
        float vn = v * si * si;
        float sb = rsqrtf(vn + 1e-5f);
        float sc = si * sb * __ldg(bn1g + ch);
        nb[tid] = make_float2(sc, -m * sc + __ldg(bn1b + ch));
    }
    fillW8(wT, w1, 128, o0, half * 64);
    __syncthreads();
    float acc[4] = {};
    gemm8n(half ? g_k : g_q, c0, wT, nb, acc);
    int c = tid & 127, rg = tid >> 7;
    int ob = o0 + rg * 4;
    float vals[4];
    if (half == 0) {
        #pragma unroll
        for (int r = 0; r < 4; r++) {
            vals[r] = acc[r];
            g_A[(ob + r) * NN + c0 + c] = vals[r];
        }
    } else {
        #pragma unroll
        for (int r = 0; r < 4; r++) {
            vals[r] = acc[r] + __ldg(b1 + ob + r);
            g_B[(ob + r) * NN + c0 + c] = vals[r];
        }
    }
    __syncthreads();
    rowstats8(vals, o0, half ? g_sB : g_sA, half ? g_qB : g_qA);
}

// score_pre, 64x64 tiles, 512 threads. Grid (12,12).  (Sq + consts cancel in softmax.)
__global__ void __launch_bounds__(512)
k_score(const float* __restrict__ w2,
        const float* __restrict__ bn2g, const float* __restrict__ bn2b,
        float* __restrict__ out)
{
    __shared__ float As[64 * 64];
    __shared__ float Bs[64 * 64];
    __shared__ float2 scb[128];
    __shared__ float w2s[128];
    __shared__ float Sks[64];
    int tid = threadIdx.x;
    int n0 = blockIdx.y * 64, m0 = blockIdx.x * 64;
    if (tid < 128) {
        float mA = g_sA[tid] * (1.f / NN), mB = g_sB[tid] * (1.f / NN);
        float vA = g_qA[tid] * (1.f / NN) - mA * mA;
        float vB = g_qB[tid] * (1.f / NN) - mB * mB;
        float m2 = mA + mB, v2 = vA + vB;
        float si = rsqrtf(v2 + 1e-3f);
        float vn = v2 * si * si;
        float sb = rsqrtf(vn + 1e-5f);
        float sc = si * sb * __ldg(bn2g + tid);
        scb[tid] = make_float2(sc, -m2 * sc + __ldg(bn2b + tid));
        w2s[tid] = __ldg(w2 + tid);
    } else if (tid < 192) {
        Sks[tid - 128] = g_Sk[m0 + tid - 128];
    }
    __syncthreads();

    int tx = tid & 15, ty = tid >> 4;
    float acc[2][4] = {};
    #pragma unroll
    for (int ch = 0; ch < 2; ch++) {
        #pragma unroll
        for (int v = tid; v < 1024; v += 512) {
            int o = v >> 4, t4 = (v & 15) << 2;
            int og = ch * 64 + o;
            float2 sb = scb[og];
            float4 a = *(const float4*)&g_A[og * NN + n0 + t4];
            a.x = fmaf(sb.x, a.x, sb.y); a.y = fmaf(sb.x, a.y, sb.y);
            a.z = fmaf(sb.x, a.z, sb.y); a.w = fmaf(sb.x, a.w, sb.y);
            *(float4*)&As[o * 64 + t4] = a;
            float4 bv = *(const float4*)&g_B[og * NN + m0 + t4];
            bv.x *= sb.x; bv.y *= sb.x; bv.z *= sb.x; bv.w *= sb.x;
            *(float4*)&Bs[o * 64 + t4] = bv;
        }
        __syncthreads();
        #pragma unroll 4
        for (int o = 0; o < 64; o++) {
            float2 a = *(const float2*)&As[o * 64 + ty * 2];
            float4 bv = *(const float4*)&Bs[o * 64 + tx * 4];
            float w = w2s[ch * 64 + o];
            acc[0][0] = fmaf(w, fmaxf(a.x + bv.x, 0.f), acc[0][0]);
            acc[0][1] = fmaf(w, fmaxf(a.x + bv.y, 0.f), acc[0][1]);
            acc[0][2] = fmaf(w, fmaxf(a.x + bv.z, 0.f), acc[0][2]);
            acc[0][3] = fmaf(w, fmaxf(a.x + bv.w, 0.f), acc[0][3]);
            acc[1][0] = fmaf(w, fmaxf(a.y + bv.x, 0.f), acc[1][0]);
            acc[1][1] = fmaf(w, fmaxf(a.y + bv.y, 0.f), acc[1][1]);
            acc[1][2] = fmaf(w, fmaxf(a.y + bv.z, 0.f), acc[1][2]);
            acc[1][3] = fmaf(w, fmaxf(a.y + bv.w, 0.f), acc[1][3]);
        }
        __syncthreads();
    }
    #pragma unroll
    for (int rn = 0; rn < 2; rn++) {
        int n = n0 + ty * 2 + rn;
        float4 o4;
        o4.x = acc[rn][0] + Sks[tx * 4 + 0];
        o4.y = acc[rn][1] + Sks[tx * 4 + 1];
        o4.z = acc[rn][2] + Sks[tx * 4 + 2];
        o4.w = acc[rn][3] + Sks[tx * 4 + 3];
        *(float4*)&out[n * NN + m0 + tx * 4] = o4;
    }
}

// Fused softmax + AV: 4 rows per block. Grid 192 x 256.
__global__ void __launch_bounds__(256)
k_avsm(float* __restrict__ score)
{
    __shared__ float Ps[4 * 768];
    __shared__ float mred[4][2], sred[4][2];
    __shared__ float hred[128][2];
    __shared__ float tr[64 * 4];
    int b = blockIdx.x, tid = threadIdx.x;
    int n0 = b * 4;
    int wid = tid >> 5, lane = tid & 31;
    int row = wid >> 1, hf = wid & 1;

    // softmax: 2 warps per row, 12 elems per lane
    float v[12];
    const int base = (n0 + row) * NN + hf * 384 + lane;
    float mx = -1e30f;
    #pragma unroll
    for (int i = 0; i < 12; i++) { v[i] = __ldg(score + base + i * 32); mx = fmaxf(mx, v[i]); }
    mx = wmax(mx);
    if (lane == 0) mred[row][hf] = mx;
    __syncthreads();
    mx = fmaxf(mred[row][0], mred[row][1]);
    float s = 0.f;
    #pragma unroll
    for (int i = 0; i < 12; i++) { v[i] = __expf(v[i] - mx); s += v[i]; }
    s = wsum(s);
    if (lane == 0) sred[row][hf] = s;
    __syncthreads();
    float inv = 1.f / (sred[row][0] + sred[row][1]);
    #pragma unroll
    for (int i = 0; i < 12; i++) {
        float p = v[i] * inv;
        Ps[row * 768 + hf * 384 + lane + i * 32] = p;
        score[base + i * 32] = p;
    }
    __syncthreads();

    // AV: split-m, thread = (mh, n, d-pair)
    int mh = tid >> 7, nn = (tid >> 5) & 3, dp = tid & 31;
    int d0 = dp * 2;
    const float* psp = Ps + nn * 768 + mh * 384;
    float a0 = 0.f, a1 = 0.f;
    #pragma unroll 8
    for (int m = 0; m < 384; m++) {
        float2 vv = __ldg((const float2*)(g_vT + (mh * 384 + m) * 64 + d0));
        float p = psp[m];
        a0 = fmaf(p, vv.x, a0); a1 = fmaf(p, vv.y, a1);
    }
    if (mh == 1) { hred[nn * 32 + dp][0] = a0; hred[nn * 32 + dp][1] = a1; }
    __syncthreads();
    if (mh == 0) {
        a0 += hred[nn * 32 + dp][0];
        a1 += hred[nn * 32 + dp][1];
        tr[d0 * 4 + nn] = a0;
        tr[(d0 + 1) * 4 + nn] = a1;
    }
    __syncthreads();
    if (tid < 64) *(float4*)&g_av[tid * NN + n0] = *(float4*)&tr[tid * 4];
}

// g1 = cw1[:,:64]@desc1 + W'@av + b'; bn1d stats atomics. Grid 96 x 256.
__global__ void k_g1(const float* __restrict__ cw1, const float* __restrict__ desc1)
{
    __shared__ float wT[512];
    int b = blockIdx.x, tid = threadIdx.x;
    int o0 = (b / 6) * 8, c0 = (b % 6) * 128;
    float acc[4] = {};
    fillW8(wT, cw1, 128, o0, 0);
    __syncthreads();
    gemm8p(desc1, c0, wT, acc);
    __syncthreads();
    fillW8(wT, g_Wp, 64, o0, 0);
    __syncthreads();
    gemm8p(g_av, c0, wT, acc);
    int c = tid & 127, rg = tid >> 7;
    int ob = o0 + rg * 4;
    float vals[4];
    #pragma unroll
    for (int r = 0; r < 4; r++) {
        vals[r] = acc[r] + g_bp[ob + r];
        g_g1[(ob + r) * NN + c0 + c] = vals[r];
    }
    __syncthreads();
    rowstats8(vals, o0, g_sG, g_qG);
}

// out_desc = desc1 + cw2 @ relu(norm(g1)) + cb2. 4-row tiles, Grid 96 x 256.
__global__ void k_final(const float* __restrict__ cw2, const float* __restrict__ cb2,
                        const float* __restrict__ cbg, const float* __restrict__ cbb,
                        const float* __restrict__ desc1, float* __restrict__ out)
{
    __shared__ float wT[256];
    __shared__ float2 ncf[128];
    int b = blockIdx.x, tid = threadIdx.x;
    int o0 = (b / 6) * 4, c0 = (b % 6) * 128;
    if (tid < 128) {
        float m = g_sG[tid] * (1.f / NN);
        float v = g_qG[tid] * (1.f / NN) - m * m;
        float sc = rsqrtf(v + 1e-5f) * __ldg(cbg + tid);
        ncf[tid] = make_float2(sc, -m * sc + __ldg(cbb + tid));
    }
    float acc[2] = {};
    fillW4(wT, cw2, 128, o0, 0);
    __syncthreads();
    gemm4n(g_g1, c0, wT, ncf, acc);
    __syncthreads();
    fillW4(wT, cw2, 128, o0, 64);
    __syncthreads();
    gemm4n(g_g1 + 64 * NN, c0, wT, ncf + 64, acc);
    int c = tid & 127, rg = tid >> 7;
    int ob = o0 + rg * 2;
    #pragma unroll
    for (int r = 0; r < 2; r++)
        out[(ob + r) * NN + c0 + c] =
            acc[r] + __ldg(cb2 + ob + r) + __ldg(desc1 + (ob + r) * NN + c0 + c);
}

// ---------------- launch ----------------
extern "C" void kernel_launch(void* const* d_in, const int* in_sizes, int n_in,
                              void* d_out, int out_size)
{
    const float* desc1 = (const float*)d_in[0];
    const float* desc2 = (const float*)d_in[1];
    const float* qw  = (const float*)d_in[2];  const float* qb  = (const float*)d_in[3];
    const float* kw  = (const float*)d_in[4];  const float* kb  = (const float*)d_in[5];
    const float* vw  = (const float*)d_in[6];  const float* vb  = (const float*)d_in[7];
    const float* mhw = (const float*)d_in[8];  const float* mhb = (const float*)d_in[9];
    const float* cw1 = (const float*)d_in[10]; const float* cb1 = (const float*)d_in[11];
    const float* cbg = (const float*)d_in[12]; const float* cbb = (const float*)d_in[13];
    const float* cw2 = (const float*)d_in[14]; const float* cb2 = (const float*)d_in[15];
    const float* shw = (const float*)d_in[16];
    const float* bn1g = (const float*)d_in[18]; const float* bn1b = (const float*)d_in[19];
    const float* sw1 = (const float*)d_in[20]; const float* sb1 = (const float*)d_in[21];
    const float* bn2g = (const float*)d_in[22]; const float* bn2b = (const float*)d_in[23];
    const float* sw2 = (const float*)d_in[24];

    float* out = (float*)d_out;
    float* out_desc  = out;
    float* out_score = out + 64 * NN;

    k_zero<<<7, 256>>>();
    k_qkv<<<161, 256>>>(desc1, desc2, qw, qb, kw, kb, vw, vb, mhw, mhb, cw1, cb1, shw);
    k_AB<<<192, 256>>>(sw1, sb1, bn1g, bn1b);
    k_score<<<dim3(12, 12), 512>>>(sw2, bn2g, bn2b, out_score);
    k_avsm<<<192, 256>>>(out_score);
    k_g1<<<96, 256>>>(cw1, desc1);
    k_final<<<96, 256>>>(cw2, cb2, cbg, cbb, desc1, out_desc);
}

// round 12
// speedup vs baseline: 1.2493x; 1.2268x over previous
#include <cuda_runtime.h>
#include <math.h>

#define NN 768

// ---------------- scratch ----------------
__device__ float g_q[64*NN], g_k[64*NN], g_vT[NN*64];
__device__ float g_A[128*NN], g_B[128*NN];
__device__ float g_avp[4*64*NN], g_g1[128*NN];
__device__ float g_Wp[128*64], g_bp[128];
__device__ float g_Sk[NN];
__device__ float g_s1[128], g_q1[128];
__device__ float g_sA[128], g_qA[128], g_sB[128], g_qB[128];
__device__ float g_sG[128], g_qG[128];

// ---------------- helpers ----------------
__device__ __forceinline__ float wsum(float v) {
    #pragma unroll
    for (int o = 16; o; o >>= 1) v += __shfl_xor_sync(0xffffffffu, v, o);
    return v;
}

// wT[i*8+r] = W[(o0+r)*ldw + koff + i]
__device__ __forceinline__ void fillW8(float* wT, const float* __restrict__ W,
                                       int ldw, int o0, int koff) {
    #pragma unroll
    for (int v = threadIdx.x; v < 512; v += 256) {
        int i = v >> 3, r = v & 7;
        wT[v] = W[(o0 + r) * ldw + koff + i];
    }
}
// wT[i*4+r]
__device__ __forceinline__ void fillW4(float* wT, const float* __restrict__ W,
                                       int ldw, int o0, int koff) {
    if (threadIdx.x < 256) {
        int i = threadIdx.x >> 2, r = threadIdx.x & 3;
        wT[threadIdx.x] = W[(o0 + r) * ldw + koff + i];
    }
}

// 8 rows x 128 cols, K=64, X streamed. acc[4].
__device__ __forceinline__ void gemm8p(const float* __restrict__ X, int c0,
                                       const float* wT, float acc[4]) {
    int c = threadIdx.x & 127, rg = threadIdx.x >> 7;
    const float* xp = X + c0 + c;
    const float* wp = wT + rg * 4;
    #pragma unroll 8
    for (int i = 0; i < 64; i++) {
        float x = __ldg(xp + i * NN);
        float4 w = *(const float4*)(wp + i * 8);
        acc[0] = fmaf(w.x, x, acc[0]); acc[1] = fmaf(w.y, x, acc[1]);
        acc[2] = fmaf(w.z, x, acc[2]); acc[3] = fmaf(w.w, x, acc[3]);
    }
}
// Same with relu(nb[i].x*x+nb[i].y) on load.
__device__ __forceinline__ void gemm8n(const float* __restrict__ X, int c0,
                                       const float* wT, const float2* nb, float acc[4]) {
    int c = threadIdx.x & 127, rg = threadIdx.x >> 7;
    const float* xp = X + c0 + c;
    const float* wp = wT + rg * 4;
    #pragma unroll 8
    for (int i = 0; i < 64; i++) {
        float2 sb = nb[i];
        float x = fmaxf(fmaf(sb.x, __ldg(xp + i * NN), sb.y), 0.f);
        float4 w = *(const float4*)(wp + i * 8);
        acc[0] = fmaf(w.x, x, acc[0]); acc[1] = fmaf(w.y, x, acc[1]);
        acc[2] = fmaf(w.z, x, acc[2]); acc[3] = fmaf(w.w, x, acc[3]);
    }
}
// 8 rows, X = sum of 4 split-k partials at stride S.
template<int S>
__device__ __forceinline__ void gemm8s4(const float* __restrict__ X, int c0,
                                        const float* wT, float acc[4]) {
    int c = threadIdx.x & 127, rg = threadIdx.x >> 7;
    const float* xp = X + c0 + c;
    const float* wp = wT + rg * 4;
    #pragma unroll 4
    for (int i = 0; i < 64; i++) {
        float x = (__ldg(xp + i * NN) + __ldg(xp + i * NN + S)) +
                  (__ldg(xp + i * NN + 2 * S) + __ldg(xp + i * NN + 3 * S));
        float4 w = *(const float4*)(wp + i * 8);
        acc[0] = fmaf(w.x, x, acc[0]); acc[1] = fmaf(w.y, x, acc[1]);
        acc[2] = fmaf(w.z, x, acc[2]); acc[3] = fmaf(w.w, x, acc[3]);
    }
}
// 4 rows x 128 cols, K=64, norm-on-load. acc[2].
__device__ __forceinline__ void gemm4n(const float* __restrict__ X, int c0,
                                       const float* wT, const float2* nb, float acc[2]) {
    int c = threadIdx.x & 127, rg = threadIdx.x >> 7;
    const float* xp = X + c0 + c;
    const float* wp = wT + rg * 2;
    #pragma unroll 8
    for (int i = 0; i < 64; i++) {
        float2 sb = nb[i];
        float x = fmaxf(fmaf(sb.x, __ldg(xp + i * NN), sb.y), 0.f);
        float2 w = *(const float2*)(wp + i * 4);
        acc[0] = fmaf(w.x, x, acc[0]); acc[1] = fmaf(w.y, x, acc[1]);
    }
}

// Per-row (8 rows/block) sum & sumsq -> atomicAdd into sdst/qdst.
__device__ __forceinline__ void rowstats8(const float vals[4], int o0,
                                          float* sdst, float* qdst) {
    __shared__ float rs[8][4], rq[8][4];
    int wid = threadIdx.x >> 5, lane = threadIdx.x & 31, rg = threadIdx.x >> 7;
    #pragma unroll
    for (int r = 0; r < 4; r++) {
        float s = wsum(vals[r]);
        float s2 = wsum(vals[r] * vals[r]);
        if (lane == 0) { rs[rg * 4 + r][wid & 3] = s; rq[rg * 4 + r][wid & 3] = s2; }
    }
    __syncthreads();
    if (threadIdx.x < 8) {
        float s  = rs[threadIdx.x][0] + rs[threadIdx.x][1] + rs[threadIdx.x][2] + rs[threadIdx.x][3];
        float q2 = rq[threadIdx.x][0] + rq[threadIdx.x][1] + rq[threadIdx.x][2] + rq[threadIdx.x][3];
        atomicAdd(&sdst[o0 + threadIdx.x], s);
        atomicAdd(&qdst[o0 + threadIdx.x], q2);
    }
}

// ---------------- kernels ----------------

// Zero all stats accumulators. Grid 7 x 256.
__global__ void k_zero()
{
    int t = blockIdx.x * 256 + threadIdx.x;
    if (t < 768) g_Sk[t] = 0.f;
    else if (t < 896)  g_s1[t - 768]  = 0.f;
    else if (t < 1024) g_q1[t - 896]  = 0.f;
    else if (t < 1152) g_sA[t - 1024] = 0.f;
    else if (t < 1280) g_qA[t - 1152] = 0.f;
    else if (t < 1408) g_sB[t - 1280] = 0.f;
    else if (t < 1536) g_qB[t - 1408] = 0.f;
    else if (t < 1664) g_sG[t - 1536] = 0.f;
    else               g_qG[t - 1664] = 0.f;
}

// q/k/v convs (8x128 tiles) + stage-1 stats + Sk atomics + W', b'. Grid 161 x 256.
__global__ void k_qkv(const float* __restrict__ d1, const float* __restrict__ d2,
                      const float* __restrict__ qw, const float* __restrict__ qb,
                      const float* __restrict__ kw, const float* __restrict__ kb,
                      const float* __restrict__ vw, const float* __restrict__ vb,
                      const float* __restrict__ mhw, const float* __restrict__ mhb,
                      const float* __restrict__ cw1, const float* __restrict__ cb1,
                      const float* __restrict__ shw)
{
    __shared__ float wT[512];
    __shared__ float skred[128];
    int b = blockIdx.x, tid = threadIdx.x;
    if (b < 144) {
        int grp = b / 48, lb = b % 48;
        int o0 = (lb / 6) * 8, c0 = (lb % 6) * 128;
        const float *W, *X, *Bb;
        if (grp == 0)      { W = qw; X = d1; Bb = qb; }
        else if (grp == 1) { W = kw; X = d2; Bb = kb; }
        else               { W = vw; X = d2; Bb = vb; }
        fillW8(wT, W, 64, o0, 0);
        __syncthreads();
        float acc[4] = {};
        gemm8p(X, c0, wT, acc);
        int c = tid & 127, rg = tid >> 7;
        int ob = o0 + rg * 4;
        float vals[4];
        #pragma unroll
        for (int r = 0; r < 4; r++) vals[r] = acc[r] + __ldg(Bb + ob + r);
        if (grp == 0) {
            #pragma unroll
            for (int r = 0; r < 4; r++) g_q[(ob + r) * NN + c0 + c] = vals[r];
            __syncthreads();
            rowstats8(vals, o0, g_s1, g_q1);
        } else if (grp == 1) {
            #pragma unroll
            for (int r = 0; r < 4; r++) g_k[(ob + r) * NN + c0 + c] = vals[r];
            float p = 0.f;
            #pragma unroll
            for (int r = 0; r < 4; r++) p = fmaf(__ldg(shw + 64 + ob + r), vals[r], p);
            if (rg == 1) skred[c] = p;
            __syncthreads();
            if (rg == 0) atomicAdd(&g_Sk[c0 + c], p + skred[c]);
            __syncthreads();
            rowstats8(vals, 64 + o0, g_s1, g_q1);
        } else {
            float4 vv;
            vv.x = vals[0]; vv.y = vals[1]; vv.z = vals[2]; vv.w = vals[3];
            *(float4*)&g_vT[(c0 + c) * 64 + ob] = vv;
        }
    } else if (b < 160) {
        int r0 = (b - 144) * 8;
        int d = tid & 63, rg = tid >> 6;
        int row = r0 + rg * 2;
        float a0 = 0.f, a1 = 0.f;
        #pragma unroll 8
        for (int i = 0; i < 64; i++) {
            float x = __ldg(mhw + i * 64 + d);
            a0 = fmaf(__ldg(cw1 + row * 128 + 64 + i), x, a0);
            a1 = fmaf(__ldg(cw1 + (row + 1) * 128 + 64 + i), x, a1);
        }
        g_Wp[row * 64 + d] = a0;
        g_Wp[(row + 1) * 64 + d] = a1;
    } else {
        if (tid < 128) {
            float s = __ldg(cb1 + tid);
            #pragma unroll 8
            for (int i = 0; i < 64; i++)
                s = fmaf(__ldg(cw1 + tid * 128 + 64 + i), __ldg(mhb + i), s);
            g_bp[tid] = s;
        }
    }
}

// A/B GEMM (8x128 tiles), stage-1 coeffs from accums, stage-2 stats atomics. Grid 192.
__global__ void k_AB(const float* __restrict__ w1, const float* __restrict__ b1,
                     const float* __restrict__ bn1g, const float* __restrict__ bn1b)
{
    __shared__ float wT[512];
    __shared__ float2 nb[64];
    int b = blockIdx.x, tid = threadIdx.x;
    int half = b / 96, lb = b % 96;
    int o0 = (lb / 6) * 8, c0 = (lb % 6) * 128;
    if (tid < 64) {
        int ch = half * 64 + tid;
        float m = g_s1[ch] * (1.f / NN);
        float v = g_q1[ch] * (1.f / NN) - m * m;
        float si = rsqrtf(v + 1e-3f);
        float vn = v * si * si;
        float sb = rsqrtf(vn + 1e-5f);
        float sc = si * sb * __ldg(bn1g + ch);
        nb[tid] = make_float2(sc, -m * sc + __ldg(bn1b + ch));
    }
    fillW8(wT, w1, 128, o0, half * 64);
    __syncthreads();
    float acc[4] = {};
    gemm8n(half ? g_k : g_q, c0, wT, nb, acc);
    int c = tid & 127, rg = tid >> 7;
    int ob = o0 + rg * 4;
    float vals[4];
    if (half == 0) {
        #pragma unroll
        for (int r = 0; r < 4; r++) {
            vals[r] = acc[r];
            g_A[(ob + r) * NN + c0 + c] = vals[r];
        }
    } else {
        #pragma unroll
        for (int r = 0; r < 4; r++) {
            vals[r] = acc[r] + __ldg(b1 + ob + r);
            g_B[(ob + r) * NN + c0 + c] = vals[r];
        }
    }
    __syncthreads();
    rowstats8(vals, o0, half ? g_sB : g_sA, half ? g_qB : g_qA);
}

// score_pre, 64x64 tiles, 256 threads, 4x4 register tiles, o-chunked by 64. Grid (12,12).
__global__ void __launch_bounds__(256)
k_score(const float* __restrict__ w2,
        const float* __restrict__ bn2g, const float* __restrict__ bn2b,
        float* __restrict__ out)
{
    __shared__ float As[64 * 64];
    __shared__ float Bs[64 * 64];
    __shared__ float w2s[128];
    __shared__ float Sks[64];
    __shared__ float2 scb[128];
    int tid = threadIdx.x;
    int n0 = blockIdx.y * 64, m0 = blockIdx.x * 64;
    if (tid < 128) {
        float mA = g_sA[tid] * (1.f / NN), mB = g_sB[tid] * (1.f / NN);
        float vA = g_qA[tid] * (1.f / NN) - mA * mA;
        float vB = g_qB[tid] * (1.f / NN) - mB * mB;
        float m2 = mA + mB, v2 = vA + vB;
        float si = rsqrtf(v2 + 1e-3f);
        float vn = v2 * si * si;
        float sb = rsqrtf(vn + 1e-5f);
        float sc = si * sb * __ldg(bn2g + tid);
        scb[tid] = make_float2(sc, -m2 * sc + __ldg(bn2b + tid));
        w2s[tid] = __ldg(w2 + tid);
    } else if (tid < 192) {
        Sks[tid - 128] = g_Sk[m0 + tid - 128];
    }
    __syncthreads();

    int tx = tid & 15, ty = tid >> 4;     // 4 m, 4 n per thread
    float acc[4][4] = {};
    #pragma unroll
    for (int chk = 0; chk < 2; chk++) {
        // fill As/Bs for this 64-o chunk: 1024 float4 each / 256 thr = 4 each
        #pragma unroll
        for (int v = tid; v < 1024; v += 256) {
            int o = v >> 4, j4 = (v & 15) << 2;
            int og = chk * 64 + o;
            float2 sb = scb[og];
            float4 a = *(const float4*)&g_A[og * NN + n0 + j4];
            a.x = fmaf(sb.x, a.x, sb.y); a.y = fmaf(sb.x, a.y, sb.y);
            a.z = fmaf(sb.x, a.z, sb.y); a.w = fmaf(sb.x, a.w, sb.y);
            *(float4*)&As[o * 64 + j4] = a;
            float4 bv = *(const float4*)&g_B[og * NN + m0 + j4];
            bv.x *= sb.x; bv.y *= sb.x; bv.z *= sb.x; bv.w *= sb.x;
            *(float4*)&Bs[o * 64 + j4] = bv;
        }
        __syncthreads();
        #pragma unroll 2
        for (int o = 0; o < 64; o++) {
            float4 a = *(const float4*)&As[o * 64 + ty * 4];
            float4 bv = *(const float4*)&Bs[o * 64 + tx * 4];
            float w = w2s[chk * 64 + o];
            #pragma unroll
            for (int rn = 0; rn < 4; rn++) {
                float av = (rn == 0) ? a.x : (rn == 1) ? a.y : (rn == 2) ? a.z : a.w;
                acc[rn][0] = fmaf(w, fmaxf(av + bv.x, 0.f), acc[rn][0]);
                acc[rn][1] = fmaf(w, fmaxf(av + bv.y, 0.f), acc[rn][1]);
                acc[rn][2] = fmaf(w, fmaxf(av + bv.z, 0.f), acc[rn][2]);
                acc[rn][3] = fmaf(w, fmaxf(av + bv.w, 0.f), acc[rn][3]);
            }
        }
        __syncthreads();
    }
    #pragma unroll
    for (int rn = 0; rn < 4; rn++) {
        int n = n0 + ty * 4 + rn;
        float4 o4;
        o4.x = acc[rn][0] + Sks[tx * 4 + 0];
        o4.y = acc[rn][1] + Sks[tx * 4 + 1];
        o4.z = acc[rn][2] + Sks[tx * 4 + 2];
        o4.w = acc[rn][3] + Sks[tx * 4 + 3];
        *(float4*)&out[n * NN + m0 + tx * 4] = o4;
    }
}

// warp-per-row softmax, in place. Grid 96 x 256.
__global__ void k_softmax(float* __restrict__ score)
{
    int row = blockIdx.x * 8 + (threadIdx.x >> 5);
    int lane = threadIdx.x & 31;
    float* p = score + row * NN;
    float v[24];
    float mx = -1e30f;
    #pragma unroll
    for (int i = 0; i < 24; i++) { v[i] = p[lane + i * 32]; mx = fmaxf(mx, v[i]); }
    #pragma unroll
    for (int o = 16; o; o >>= 1) mx = fmaxf(mx, __shfl_xor_sync(0xffffffffu, mx, o));
    float s = 0.f;
    #pragma unroll
    for (int i = 0; i < 24; i++) { v[i] = __expf(v[i] - mx); s += v[i]; }
    s = wsum(s);
    float inv = 1.f / s;
    #pragma unroll
    for (int i = 0; i < 24; i++) p[lane + i * 32] = v[i] * inv;
}

// av partials: 48 n-tiles x 4 k-splits = 192 x 256.
__global__ void k_av(const float* __restrict__ score)
{
    int bx = blockIdx.x;
    int nt = bx % 48, ks = bx / 48;
    int n0 = nt * 16;
    int tid = threadIdx.x;
    __shared__ float Vs[64][64];
    __shared__ float Ps[16][64];
    int d0  = (tid & 31) * 2;
    int nl0 = (tid >> 5) * 2;
    float a00 = 0.f, a01 = 0.f, a10 = 0.f, a11 = 0.f;
    for (int c = 0; c < 3; c++) {
        int mb = ks * 192 + c * 64;
        for (int idx = tid; idx < 64 * 64; idx += 256)
            Vs[idx >> 6][idx & 63] = g_vT[(mb + (idx >> 6)) * 64 + (idx & 63)];
        for (int idx = tid; idx < 16 * 64; idx += 256)
            Ps[idx >> 6][idx & 63] = score[(n0 + (idx >> 6)) * NN + mb + (idx & 63)];
        __syncthreads();
        #pragma unroll 4
        for (int m = 0; m < 64; m++) {
            float2 vv = *(const float2*)&Vs[m][d0];
            float p0 = Ps[nl0][m], p1 = Ps[nl0 + 1][m];
            a00 = fmaf(p0, vv.x, a00); a01 = fmaf(p0, vv.y, a01);
            a10 = fmaf(p1, vv.x, a10); a11 = fmaf(p1, vv.y, a11);
        }
        __syncthreads();
    }
    float* dst = g_avp + ks * (64 * NN);
    dst[d0 * NN + n0 + nl0]           = a00;
    dst[(d0 + 1) * NN + n0 + nl0]     = a01;
    dst[d0 * NN + n0 + nl0 + 1]       = a10;
    dst[(d0 + 1) * NN + n0 + nl0 + 1] = a11;
}

// g1 = cw1[:,:64]@desc1 + W'@(sum of 4 av partials) + b'; bn1d stats atomics. Grid 96.
__global__ void k_g1(const float* __restrict__ cw1, const float* __restrict__ desc1)
{
    __shared__ float wT[512];
    int b = blockIdx.x, tid = threadIdx.x;
    int o0 = (b / 6) * 8, c0 = (b % 6) * 128;
    float acc[4] = {};
    fillW8(wT, cw1, 128, o0, 0);
    __syncthreads();
    gemm8p(desc1, c0, wT, acc);
    __syncthreads();
    fillW8(wT, g_Wp, 64, o0, 0);
    __syncthreads();
    gemm8s4<64 * NN>(g_avp, c0, wT, acc);
    int c = tid & 127, rg = tid >> 7;
    int ob = o0 + rg * 4;
    float vals[4];
    #pragma unroll
    for (int r = 0; r < 4; r++) {
        vals[r] = acc[r] + g_bp[ob + r];
        g_g1[(ob + r) * NN + c0 + c] = vals[r];
    }
    __syncthreads();
    rowstats8(vals, o0, g_sG, g_qG);
}

// out_desc = desc1 + cw2 @ relu(norm(g1)) + cb2. 4-row tiles, Grid 96 x 256.
__global__ void k_final(const float* __restrict__ cw2, const float* __restrict__ cb2,
                        const float* __restrict__ cbg, const float* __restrict__ cbb,
                        const float* __restrict__ desc1, float* __restrict__ out)
{
    __shared__ float wT[256];
    __shared__ float2 ncf[128];
    int b = blockIdx.x, tid = threadIdx.x;
    int o0 = (b / 6) * 4, c0 = (b % 6) * 128;
    if (tid < 128) {
        float m = g_sG[tid] * (1.f / NN);
        float v = g_qG[tid] * (1.f / NN) - m * m;
        float sc = rsqrtf(v + 1e-5f) * __ldg(cbg + tid);
        ncf[tid] = make_float2(sc, -m * sc + __ldg(cbb + tid));
    }
    float acc[2] = {};
    fillW4(wT, cw2, 128, o0, 0);
    __syncthreads();
    gemm4n(g_g1, c0, wT, ncf, acc);
    __syncthreads();
    fillW4(wT, cw2, 128, o0, 64);
    __syncthreads();
    gemm4n(g_g1 + 64 * NN, c0, wT, ncf + 64, acc);
    int c = tid & 127, rg = tid >> 7;
    int ob = o0 + rg * 2;
    #pragma unroll
    for (int r = 0; r < 2; r++)
        out[(ob + r) * NN + c0 + c] =
            acc[r] + __ldg(cb2 + ob + r) + __ldg(desc1 + (ob + r) * NN + c0 + c);
}

// ---------------- launch ----------------
extern "C" void kernel_launch(void* const* d_in, const int* in_sizes, int n_in,
                              void* d_out, int out_size)
{
    const float* desc1 = (const float*)d_in[0];
    const float* desc2 = (const float*)d_in[1];
    const float* qw  = (const float*)d_in[2];  const float* qb  = (const float*)d_in[3];
    const float* kw  = (const float*)d_in[4];  const float* kb  = (const float*)d_in[5];
    const float* vw  = (const float*)d_in[6];  const float* vb  = (const float*)d_in[7];
    const float* mhw = (const float*)d_in[8];  const float* mhb = (const float*)d_in[9];
    const float* cw1 = (const float*)d_in[10]; const float* cb1 = (const float*)d_in[11];
    const float* cbg = (const float*)d_in[12]; const float* cbb = (const float*)d_in[13];
    const float* cw2 = (const float*)d_in[14]; const float* cb2 = (const float*)d_in[15];
    const float* shw = (const float*)d_in[16];
    const float* bn1g = (const float*)d_in[18]; const float* bn1b = (const float*)d_in[19];
    const float* sw1 = (const float*)d_in[20]; const float* sb1 = (const float*)d_in[21];
    const float* bn2g = (const float*)d_in[22]; const float* bn2b = (const float*)d_in[23];
    const float* sw2 = (const float*)d_in[24];

    float* out = (float*)d_out;
    float* out_desc  = out;
    float* out_score = out + 64 * NN;

    k_zero<<<7, 256>>>();
    k_qkv<<<161, 256>>>(desc1, desc2, qw, qb, kw, kb, vw, vb, mhw, mhb, cw1, cb1, shw);
    k_AB<<<192, 256>>>(sw1, sb1, bn1g, bn1b);
    k_score<<<dim3(12, 12), 256>>>(sw2, bn2g, bn2b, out_score);
    k_softmax<<<96, 256>>>(out_score);
    k_av<<<192, 256>>>(out_score);
    k_g1<<<96, 256>>>(cw1, desc1);
    k_final<<<96, 256>>>(cw2, cb2, cbg, cbb, desc1, out_desc);
}

// round 13
// speedup vs baseline: 1.3594x; 1.0881x over previous
#include <cuda_runtime.h>
#include <math.h>

#define NN 768

// ---------------- scratch ----------------
__device__ float g_q[64*NN], g_k[64*NN], g_vT[NN*64];
__device__ float g_A[128*NN], g_B[128*NN];
__device__ float g_avp[4*64*NN], g_g1[128*NN];
__device__ float g_Wp[128*64], g_bp[128];
__device__ float g_sp1[NN*NN];                 // o-split partial of score
// per-block partial stats (no atomics): [colblock 6][channel 128]
__device__ float g_s1p[6*128], g_q1p[6*128];
__device__ float g_sAp[6*128], g_qAp[6*128], g_sBp[6*128], g_qBp[6*128];
__device__ float g_sGp[6*128], g_qGp[6*128];
__device__ float g_Skp[8*NN];                  // [rowblock 8][n 768]

// ---------------- helpers ----------------
__device__ __forceinline__ float wsum(float v) {
    #pragma unroll
    for (int o = 16; o; o >>= 1) v += __shfl_xor_sync(0xffffffffu, v, o);
    return v;
}

// wT[i*8+r] = W[(o0+r)*ldw + koff + i]
__device__ __forceinline__ void fillW8(float* wT, const float* __restrict__ W,
                                       int ldw, int o0, int koff) {
    #pragma unroll
    for (int v = threadIdx.x; v < 512; v += 256) {
        int i = v >> 3, r = v & 7;
        wT[v] = W[(o0 + r) * ldw + koff + i];
    }
}
__device__ __forceinline__ void fillW4(float* wT, const float* __restrict__ W,
                                       int ldw, int o0, int koff) {
    if (threadIdx.x < 256) {
        int i = threadIdx.x >> 2, r = threadIdx.x & 3;
        wT[threadIdx.x] = W[(o0 + r) * ldw + koff + i];
    }
}

// 8 rows x 128 cols, K=64, X streamed. acc[4].
__device__ __forceinline__ void gemm8p(const float* __restrict__ X, int c0,
                                       const float* wT, float acc[4]) {
    int c = threadIdx.x & 127, rg = threadIdx.x >> 7;
    const float* xp = X + c0 + c;
    const float* wp = wT + rg * 4;
    #pragma unroll 8
    for (int i = 0; i < 64; i++) {
        float x = __ldg(xp + i * NN);
        float4 w = *(const float4*)(wp + i * 8);
        acc[0] = fmaf(w.x, x, acc[0]); acc[1] = fmaf(w.y, x, acc[1]);
        acc[2] = fmaf(w.z, x, acc[2]); acc[3] = fmaf(w.w, x, acc[3]);
    }
}
__device__ __forceinline__ void gemm8n(const float* __restrict__ X, int c0,
                                       const float* wT, const float2* nb, float acc[4]) {
    int c = threadIdx.x & 127, rg = threadIdx.x >> 7;
    const float* xp = X + c0 + c;
    const float* wp = wT + rg * 4;
    #pragma unroll 8
    for (int i = 0; i < 64; i++) {
        float2 sb = nb[i];
        float x = fmaxf(fmaf(sb.x, __ldg(xp + i * NN), sb.y), 0.f);
        float4 w = *(const float4*)(wp + i * 8);
        acc[0] = fmaf(w.x, x, acc[0]); acc[1] = fmaf(w.y, x, acc[1]);
        acc[2] = fmaf(w.z, x, acc[2]); acc[3] = fmaf(w.w, x, acc[3]);
    }
}
template<int S>
__device__ __forceinline__ void gemm8s4(const float* __restrict__ X, int c0,
                                        const float* wT, float acc[4]) {
    int c = threadIdx.x & 127, rg = threadIdx.x >> 7;
    const float* xp = X + c0 + c;
    const float* wp = wT + rg * 4;
    #pragma unroll 4
    for (int i = 0; i < 64; i++) {
        float x = (__ldg(xp + i * NN) + __ldg(xp + i * NN + S)) +
                  (__ldg(xp + i * NN + 2 * S) + __ldg(xp + i * NN + 3 * S));
        float4 w = *(const float4*)(wp + i * 8);
        acc[0] = fmaf(w.x, x, acc[0]); acc[1] = fmaf(w.y, x, acc[1]);
        acc[2] = fmaf(w.z, x, acc[2]); acc[3] = fmaf(w.w, x, acc[3]);
    }
}
__device__ __forceinline__ void gemm4n(const float* __restrict__ X, int c0,
                                       const float* wT, const float2* nb, float acc[2]) {
    int c = threadIdx.x & 127, rg = threadIdx.x >> 7;
    const float* xp = X + c0 + c;
    const float* wp = wT + rg * 2;
    #pragma unroll 8
    for (int i = 0; i < 64; i++) {
        float2 sb = nb[i];
        float x = fmaxf(fmaf(sb.x, __ldg(xp + i * NN), sb.y), 0.f);
        float2 w = *(const float2*)(wp + i * 4);
        acc[0] = fmaf(w.x, x, acc[0]); acc[1] = fmaf(w.y, x, acc[1]);
    }
}

// Per-row (8 rows/block) sum & sumsq -> plain store to unique partial slot.
__device__ __forceinline__ void rowstats8w(const float vals[4], int base,
                                           float* sdst, float* qdst) {
    __shared__ float rs[8][4], rq[8][4];
    int wid = threadIdx.x >> 5, lane = threadIdx.x & 31, rg = threadIdx.x >> 7;
    #pragma unroll
    for (int r = 0; r < 4; r++) {
        float s = wsum(vals[r]);
        float s2 = wsum(vals[r] * vals[r]);
        if (lane == 0) { rs[rg * 4 + r][wid & 3] = s; rq[rg * 4 + r][wid & 3] = s2; }
    }
    __syncthreads();
    if (threadIdx.x < 8) {
        sdst[base + threadIdx.x] = rs[threadIdx.x][0] + rs[threadIdx.x][1] +
                                   rs[threadIdx.x][2] + rs[threadIdx.x][3];
        qdst[base + threadIdx.x] = rq[threadIdx.x][0] + rq[threadIdx.x][1] +
                                   rq[threadIdx.x][2] + rq[threadIdx.x][3];
    }
}

// ---------------- kernels ----------------

// q/k/v convs (8x128 tiles) + stage-1 stat partials + Sk partials + W', b'. Grid 161.
__global__ void k_qkv(const float* __restrict__ d1, const float* __restrict__ d2,
                      const float* __restrict__ qw, const float* __restrict__ qb,
                      const float* __restrict__ kw, const float* __restrict__ kb,
                      const float* __restrict__ vw, const float* __restrict__ vb,
                      const float* __restrict__ mhw, const float* __restrict__ mhb,
                      const float* __restrict__ cw1, const float* __restrict__ cb1,
                      const float* __restrict__ shw)
{
    __shared__ float wT[512];
    __shared__ float skred[128];
    int b = blockIdx.x, tid = threadIdx.x;
    if (b < 144) {
        int grp = b / 48, lb = b % 48;
        int rp = lb / 6, cb = lb % 6;
        int o0 = rp * 8, c0 = cb * 128;
        const float *W, *X, *Bb;
        if (grp == 0)      { W = qw; X = d1; Bb = qb; }
        else if (grp == 1) { W = kw; X = d2; Bb = kb; }
        else               { W = vw; X = d2; Bb = vb; }
        fillW8(wT, W, 64, o0, 0);
        __syncthreads();
        float acc[4] = {};
        gemm8p(X, c0, wT, acc);
        int c = tid & 127, rg = tid >> 7;
        int ob = o0 + rg * 4;
        float vals[4];
        #pragma unroll
        for (int r = 0; r < 4; r++) vals[r] = acc[r] + __ldg(Bb + ob + r);
        if (grp == 0) {
            #pragma unroll
            for (int r = 0; r < 4; r++) g_q[(ob + r) * NN + c0 + c] = vals[r];
            __syncthreads();
            rowstats8w(vals, cb * 128 + o0, g_s1p, g_q1p);
        } else if (grp == 1) {
            #pragma unroll
            for (int r = 0; r < 4; r++) g_k[(ob + r) * NN + c0 + c] = vals[r];
            float p = 0.f;
            #pragma unroll
            for (int r = 0; r < 4; r++) p = fmaf(__ldg(shw + 64 + ob + r), vals[r], p);
            if (rg == 1) skred[c] = p;
            __syncthreads();
            if (rg == 0) g_Skp[rp * NN + c0 + c] = p + skred[c];
            __syncthreads();
            rowstats8w(vals, cb * 128 + 64 + o0, g_s1p, g_q1p);
        } else {
            float4 vv;
            vv.x = vals[0]; vv.y = vals[1]; vv.z = vals[2]; vv.w = vals[3];
            *(float4*)&g_vT[(c0 + c) * 64 + ob] = vv;
        }
    } else if (b < 160) {
        int r0 = (b - 144) * 8;
        int d = tid & 63, rg = tid >> 6;
        int row = r0 + rg * 2;
        float a0 = 0.f, a1 = 0.f;
        #pragma unroll 8
        for (int i = 0; i < 64; i++) {
            float x = __ldg(mhw + i * 64 + d);
            a0 = fmaf(__ldg(cw1 + row * 128 + 64 + i), x, a0);
            a1 = fmaf(__ldg(cw1 + (row + 1) * 128 + 64 + i), x, a1);
        }
        g_Wp[row * 64 + d] = a0;
        g_Wp[(row + 1) * 64 + d] = a1;
    } else {
        if (tid < 128) {
            float s = __ldg(cb1 + tid);
            #pragma unroll 8
            for (int i = 0; i < 64; i++)
                s = fmaf(__ldg(cw1 + tid * 128 + 64 + i), __ldg(mhb + i), s);
            g_bp[tid] = s;
        }
    }
}

// A/B GEMM; stage-1 coeffs from partial sums; stage-2 stat partials. Grid 192.
__global__ void k_AB(const float* __restrict__ w1, const float* __restrict__ b1,
                     const float* __restrict__ bn1g, const float* __restrict__ bn1b)
{
    __shared__ float wT[512];
    __shared__ float2 nb[64];
    int b = blockIdx.x, tid = threadIdx.x;
    int half = b / 96, lb = b % 96;
    int o0 = (lb / 6) * 8, cb = lb % 6;
    int c0 = cb * 128;
    if (tid < 64) {
        int ch = half * 64 + tid;
        float s = 0.f, q2 = 0.f;
        #pragma unroll
        for (int j = 0; j < 6; j++) { s += g_s1p[j * 128 + ch]; q2 += g_q1p[j * 128 + ch]; }
        float m = s * (1.f / NN);
        float v = q2 * (1.f / NN) - m * m;
        float si = rsqrtf(v + 1e-3f);
        float vn = v * si * si;
        float sb = rsqrtf(vn + 1e-5f);
        float sc = si * sb * __ldg(bn1g + ch);
        nb[tid] = make_float2(sc, -m * sc + __ldg(bn1b + ch));
    }
    fillW8(wT, w1, 128, o0, half * 64);
    __syncthreads();
    float acc[4] = {};
    gemm8n(half ? g_k : g_q, c0, wT, nb, acc);
    int c = tid & 127, rg = tid >> 7;
    int ob = o0 + rg * 4;
    float vals[4];
    if (half == 0) {
        #pragma unroll
        for (int r = 0; r < 4; r++) {
            vals[r] = acc[r];
            g_A[(ob + r) * NN + c0 + c] = vals[r];
        }
    } else {
        #pragma unroll
        for (int r = 0; r < 4; r++) {
            vals[r] = acc[r] + __ldg(b1 + ob + r);
            g_B[(ob + r) * NN + c0 + c] = vals[r];
        }
    }
    __syncthreads();
    rowstats8w(vals, cb * 128 + o0, half ? g_sBp : g_sAp, half ? g_qBp : g_qAp);
}

// score_pre partials, 64x64 tiles split over o (z=0: o<64 +Sk, z=1: o>=64).
// Grid (12,12,2) x 256, 4x4 register tiles, 32-o smem chunks (17KB smem).
__global__ void __launch_bounds__(256)
k_score(const float* __restrict__ w2,
        const float* __restrict__ bn2g, const float* __restrict__ bn2b,
        float* __restrict__ out)
{
    __shared__ float As[32 * 64];
    __shared__ float Bs[32 * 64];
    __shared__ float w2s[64];
    __shared__ float Sks[64];
    __shared__ float2 scb[64];
    int tid = threadIdx.x;
    int n0 = blockIdx.y * 64, m0 = blockIdx.x * 64;
    int z = blockIdx.z;
    if (tid < 64) {
        int ch = z * 64 + tid;
        float sA = 0.f, qA = 0.f, sB = 0.f, qB = 0.f;
        #pragma unroll
        for (int j = 0; j < 6; j++) {
            sA += g_sAp[j * 128 + ch]; qA += g_qAp[j * 128 + ch];
            sB += g_sBp[j * 128 + ch]; qB += g_qBp[j * 128 + ch];
        }
        float mA = sA * (1.f / NN), mB = sB * (1.f / NN);
        float vA = qA * (1.f / NN) - mA * mA;
        float vB = qB * (1.f / NN) - mB * mB;
        float m2 = mA + mB, v2 = vA + vB;
        float si = rsqrtf(v2 + 1e-3f);
        float vn = v2 * si * si;
        float sb = rsqrtf(vn + 1e-5f);
        float sc = si * sb * __ldg(bn2g + ch);
        scb[tid] = make_float2(sc, -m2 * sc + __ldg(bn2b + ch));
        w2s[tid] = __ldg(w2 + ch);
    } else if (tid < 128) {
        int mm = tid - 64;
        float s = 0.f;
        #pragma unroll
        for (int rp = 0; rp < 8; rp++) s += g_Skp[rp * NN + m0 + mm];
        Sks[mm] = s;
    }
    __syncthreads();

    int tx = tid & 15, ty = tid >> 4;     // 4 m, 4 n per thread
    float acc[4][4] = {};
    #pragma unroll
    for (int chk = 0; chk < 2; chk++) {
        #pragma unroll
        for (int v = tid; v < 512; v += 256) {
            int o = v >> 4, j4 = (v & 15) << 2;
            int ol = chk * 32 + o;               // 0..63 within this z-half
            int og = z * 64 + ol;
            float2 sb = scb[ol];
            float4 a = *(const float4*)&g_A[og * NN + n0 + j4];
            a.x = fmaf(sb.x, a.x, sb.y); a.y = fmaf(sb.x, a.y, sb.y);
            a.z = fmaf(sb.x, a.z, sb.y); a.w = fmaf(sb.x, a.w, sb.y);
            *(float4*)&As[o * 64 + j4] = a;
            float4 bv = *(const float4*)&g_B[og * NN + m0 + j4];
            bv.x *= sb.x; bv.y *= sb.x; bv.z *= sb.x; bv.w *= sb.x;
            *(float4*)&Bs[o * 64 + j4] = bv;
        }
        __syncthreads();
        #pragma unroll 2
        for (int o = 0; o < 32; o++) {
            float4 a = *(const float4*)&As[o * 64 + ty * 4];
            float4 bv = *(const float4*)&Bs[o * 64 + tx * 4];
            float w = w2s[chk * 32 + o];
            #pragma unroll
            for (int rn = 0; rn < 4; rn++) {
                float av = (rn == 0) ? a.x : (rn == 1) ? a.y : (rn == 2) ? a.z : a.w;
                acc[rn][0] = fmaf(w, fmaxf(av + bv.x, 0.f), acc[rn][0]);
                acc[rn][1] = fmaf(w, fmaxf(av + bv.y, 0.f), acc[rn][1]);
                acc[rn][2] = fmaf(w, fmaxf(av + bv.z, 0.f), acc[rn][2]);
                acc[rn][3] = fmaf(w, fmaxf(av + bv.w, 0.f), acc[rn][3]);
            }
        }
        __syncthreads();
    }
    float* dst = z ? g_sp1 : out;
    #pragma unroll
    for (int rn = 0; rn < 4; rn++) {
        int n = n0 + ty * 4 + rn;
        float4 o4;
        if (z == 0) {
            o4.x = acc[rn][0] + Sks[tx * 4 + 0];
            o4.y = acc[rn][1] + Sks[tx * 4 + 1];
            o4.z = acc[rn][2] + Sks[tx * 4 + 2];
            o4.w = acc[rn][3] + Sks[tx * 4 + 3];
        } else {
            o4.x = acc[rn][0]; o4.y = acc[rn][1];
            o4.z = acc[rn][2]; o4.w = acc[rn][3];
        }
        *(float4*)&dst[n * NN + m0 + tx * 4] = o4;
    }
}

// warp-per-row softmax over (score + partial1), in place. Grid 96 x 256.
__global__ void k_softmax(float* __restrict__ score)
{
    int row = blockIdx.x * 8 + (threadIdx.x >> 5);
    int lane = threadIdx.x & 31;
    float* p = score + row * NN;
    const float* p1 = g_sp1 + row * NN;
    float v[24];
    float mx = -1e30f;
    #pragma unroll
    for (int i = 0; i < 24; i++) {
        v[i] = p[lane + i * 32] + __ldg(p1 + lane + i * 32);
        mx = fmaxf(mx, v[i]);
    }
    #pragma unroll
    for (int o = 16; o; o >>= 1) mx = fmaxf(mx, __shfl_xor_sync(0xffffffffu, mx, o));
    float s = 0.f;
    #pragma unroll
    for (int i = 0; i < 24; i++) { v[i] = __expf(v[i] - mx); s += v[i]; }
    s = wsum(s);
    float inv = 1.f / s;
    #pragma unroll
    for (int i = 0; i < 24; i++) p[lane + i * 32] = v[i] * inv;
}

// av partials: 48 n-tiles x 4 k-splits = 192 x 256.
__global__ void k_av(const float* __restrict__ score)
{
    int bx = blockIdx.x;
    int nt = bx % 48, ks = bx / 48;
    int n0 = nt * 16;
    int tid = threadIdx.x;
    __shared__ float Vs[64][64];
    __shared__ float Ps[16][64];
    int d0  = (tid & 31) * 2;
    int nl0 = (tid >> 5) * 2;
    float a00 = 0.f, a01 = 0.f, a10 = 0.f, a11 = 0.f;
    for (int c = 0; c < 3; c++) {
        int mb = ks * 192 + c * 64;
        for (int idx = tid; idx < 64 * 64; idx += 256)
            Vs[idx >> 6][idx & 63] = g_vT[(mb + (idx >> 6)) * 64 + (idx & 63)];
        for (int idx = tid; idx < 16 * 64; idx += 256)
            Ps[idx >> 6][idx & 63] = score[(n0 + (idx >> 6)) * NN + mb + (idx & 63)];
        __syncthreads();
        #pragma unroll 4
        for (int m = 0; m < 64; m++) {
            float2 vv = *(const float2*)&Vs[m][d0];
            float p0 = Ps[nl0][m], p1 = Ps[nl0 + 1][m];
            a00 = fmaf(p0, vv.x, a00); a01 = fmaf(p0, vv.y, a01);
            a10 = fmaf(p1, vv.x, a10); a11 = fmaf(p1, vv.y, a11);
        }
        __syncthreads();
    }
    float* dst = g_avp + ks * (64 * NN);
    dst[d0 * NN + n0 + nl0]           = a00;
    dst[(d0 + 1) * NN + n0 + nl0]     = a01;
    dst[d0 * NN + n0 + nl0 + 1]       = a10;
    dst[(d0 + 1) * NN + n0 + nl0 + 1] = a11;
}

// g1 = cw1[:,:64]@desc1 + W'@(sum of 4 av partials) + b'; bn1d stat partials. Grid 96.
__global__ void k_g1(const float* __restrict__ cw1, const float* __restrict__ desc1)
{
    __shared__ float wT[512];
    int b = blockIdx.x, tid = threadIdx.x;
    int o0 = (b / 6) * 8, cb = b % 6;
    int c0 = cb * 128;
    float acc[4] = {};
    fillW8(wT, cw1, 128, o0, 0);
    __syncthreads();
    gemm8p(desc1, c0, wT, acc);
    __syncthreads();
    fillW8(wT, g_Wp, 64, o0, 0);
    __syncthreads();
    gemm8s4<64 * NN>(g_avp, c0, wT, acc);
    int c = tid & 127, rg = tid >> 7;
    int ob = o0 + rg * 4;
    float vals[4];
    #pragma unroll
    for (int r = 0; r < 4; r++) {
        vals[r] = acc[r] + g_bp[ob + r];
        g_g1[(ob + r) * NN + c0 + c] = vals[r];
    }
    __syncthreads();
    rowstats8w(vals, cb * 128 + o0, g_sGp, g_qGp);
}

// out_desc = desc1 + cw2 @ relu(norm(g1)) + cb2. 4-row tiles, Grid 96 x 256.
__global__ void k_final(const float* __restrict__ cw2, const float* __restrict__ cb2,
                        const float* __restrict__ cbg, const float* __restrict__ cbb,
                        const float* __restrict__ desc1, float* __restrict__ out)
{
    __shared__ float wT[256];
    __shared__ float2 ncf[128];
    int b = blockIdx.x, tid = threadIdx.x;
    int o0 = (b / 6) * 4, c0 = (b % 6) * 128;
    if (tid < 128) {
        float s = 0.f, q2 = 0.f;
        #pragma unroll
        for (int j = 0; j < 6; j++) { s += g_sGp[j * 128 + tid]; q2 += g_qGp[j * 128 + tid]; }
        float m = s * (1.f / NN);
        float v = q2 * (1.f / NN) - m * m;
        float sc = rsqrtf(v + 1e-5f) * __ldg(cbg + tid);
        ncf[tid] = make_float2(sc, -m * sc + __ldg(cbb + tid));
    }
    float acc[2] = {};
    fillW4(wT, cw2, 128, o0, 0);
    __syncthreads();
    gemm4n(g_g1, c0, wT, ncf, acc);
    __syncthreads();
    fillW4(wT, cw2, 128, o0, 64);
    __syncthreads();
    gemm4n(g_g1 + 64 * NN, c0, wT, ncf + 64, acc);
    int c = tid & 127, rg = tid >> 7;
    int ob = o0 + rg * 2;
    #pragma unroll
    for (int r = 0; r < 2; r++)
        out[(ob + r) * NN + c0 + c] =
            acc[r] + __ldg(cb2 + ob + r) + __ldg(desc1 + (ob + r) * NN + c0 + c);
}

// ---------------- launch ----------------
extern "C" void kernel_launch(void* const* d_in, const int* in_sizes, int n_in,
                              void* d_out, int out_size)
{
    const float* desc1 = (const float*)d_in[0];
    const float* desc2 = (const float*)d_in[1];
    const float* qw  = (const float*)d_in[2];  const float* qb  = (const float*)d_in[3];
    const float* kw  = (const float*)d_in[4];  const float* kb  = (const float*)d_in[5];
    const float* vw  = (const float*)d_in[6];  const float* vb  = (const float*)d_in[7];
    const float* mhw = (const float*)d_in[8];  const float* mhb = (const float*)d_in[9];
    const float* cw1 = (const float*)d_in[10]; const float* cb1 = (const float*)d_in[11];
    const float* cbg = (const float*)d_in[12]; const float* cbb = (const float*)d_in[13];
    const float* cw2 = (const float*)d_in[14]; const float* cb2 = (const float*)d_in[15];
    const float* shw = (const float*)d_in[16];
    const float* bn1g = (const float*)d_in[18]; const float* bn1b = (const float*)d_in[19];
    const float* sw1 = (const float*)d_in[20]; const float* sb1 = (const float*)d_in[21];
    const float* bn2g = (const float*)d_in[22]; const float* bn2b = (const float*)d_in[23];
    const float* sw2 = (const float*)d_in[24];

    float* out = (float*)d_out;
    float* out_desc  = out;
    float* out_score = out + 64 * NN;

    k_qkv<<<161, 256>>>(desc1, desc2, qw, qb, kw, kb, vw, vb, mhw, mhb, cw1, cb1, shw);
    k_AB<<<192, 256>>>(sw1, sb1, bn1g, bn1b);
    k_score<<<dim3(12, 12, 2), 256>>>(sw2, bn2g, bn2b, out_score);
    k_softmax<<<96, 256>>>(out_score);
    k_av<<<192, 256>>>(out_score);
    k_g1<<<96, 256>>>(cw1, desc1);
    k_final<<<96, 256>>>(cw2, cb2, cbg, cbb, desc1, out_desc);
}